// round 1
// baseline (speedup 1.0000x reference)
#include <cuda_runtime.h>
#include <math.h>

// Problem constants (fixed by the reference)
#define N_K        16
#define C_CAT      136          // 16*17/2 upper-tri pairs
#define DIM        64
#define NROWS      8192         // 512 * 16
#define ROWS_PER_BLK 8
#define MAIN_BLOCKS (NROWS / ROWS_PER_BLK)   // 1024

#define LOG2PI_F   1.8378770664093453f
#define NEG_RSQRT2 (-0.70710678118654752440f)

// ---- device scratch (static globals; no allocation) ----
__device__ float d_partials[MAIN_BLOCKS];

struct PerC {
    float recip [C_CAT];
    float invsig[C_CAT];
    float sq    [C_CAT];   // sqrt(clip(inv_sig))
    float base  [C_CAT];   // lp (+ 0.5*(log2pi - log(clip_is)) for non-diag)
    float k1    [C_CAT];   // dot(alpha_c, mu_B)
    float mB2   [C_CAT];   // |mu_B|^2
    int   ab    [C_CAT];   // A | B<<8 | diag<<16
};
__device__ PerC d_c;

// ---------------------------------------------------------------------------
// Kernel 1: softmax(pi) + per-category constants.  One block, trivial cost.
// ---------------------------------------------------------------------------
__global__ void precompute_kernel(const float* __restrict__ pi,
                                  const float* __restrict__ mu)
{
    __shared__ float red[256];
    __shared__ float s_max, s_sum;
    int t = threadIdx.x;

    float v = (t < C_CAT) ? pi[t] : -INFINITY;
    red[t] = v; __syncthreads();
    for (int o = 128; o; o >>= 1) { if (t < o) red[t] = fmaxf(red[t], red[t + o]); __syncthreads(); }
    if (t == 0) s_max = red[0];
    __syncthreads();

    float e = (t < C_CAT) ? expf(v - s_max) : 0.f;
    red[t] = e; __syncthreads();
    for (int o = 128; o; o >>= 1) { if (t < o) red[t] += red[t + o]; __syncthreads(); }
    if (t == 0) s_sum = red[0];
    __syncthreads();

    if (t < C_CAT) {
        float tp = fminf(fmaxf(e / s_sum, 1e-16f), 1.0f);
        float lp = -32.0f * LOG2PI_F + logf(tp);   // -0.5*d*log2pi + log(temp_pi)

        // c -> (A,B) upper-tri, row-major (matches np.nonzero(np.triu(...)))
        int A = 0, rem = t;
        while (rem >= (N_K - A)) { rem -= (N_K - A); ++A; }
        int B = A + rem;

        float invsig = 0.f, k1 = 0.f, mB2 = 0.f;
        #pragma unroll
        for (int d = 0; d < DIM; ++d) {
            float mb = mu[d * N_K + B];
            float ma = mu[d * N_K + A];
            float a  = mb - ma;
            invsig = fmaf(a, a, invsig);
            k1     = fmaf(a, mb, k1);
            mB2    = fmaf(mb, mb, mB2);
        }
        float clip_is = fminf(fmaxf(invsig, 1e-12f), 1e30f);
        float sq = sqrtf(clip_is);
        float c0 = 0.5f * (LOG2PI_F - logf(clip_is));
        int diag = (invsig == 0.0f) ? 1 : 0;

        d_c.recip [t] = diag ? 0.f : (1.0f / invsig);
        d_c.invsig[t] = invsig;
        d_c.sq    [t] = sq;
        d_c.base  [t] = diag ? lp : (lp + c0);
        d_c.k1    [t] = k1;
        d_c.mB2   [t] = mB2;
        d_c.ab    [t] = A | (B << 8) | (diag << 16);
    }
}

// ---------------------------------------------------------------------------
// Kernel 2: main. One warp per (b,l) row; lanes split the 136 categories.
// ---------------------------------------------------------------------------
__global__ __launch_bounds__(256) void main_kernel(const float* __restrict__ z,
                                                   const float* __restrict__ mu)
{
    __shared__ float mu_s[DIM][N_K];               // 4 KB
    __shared__ float z_s [ROWS_PER_BLK][DIM];      // 2 KB
    __shared__ float g_s [ROWS_PER_BLK][N_K];      // 512 B
    __shared__ float rowres[ROWS_PER_BLK];
    __shared__ float c_recip[C_CAT], c_invsig[C_CAT], c_sq[C_CAT],
                     c_base[C_CAT], c_k1[C_CAT], c_mB2[C_CAT];
    __shared__ int   c_ab[C_CAT];

    const int t = threadIdx.x;

    // stage mu
    for (int i = t; i < DIM * N_K; i += 256)
        (&mu_s[0][0])[i] = mu[i];
    // stage this block's 8 z-rows
    const int row0 = blockIdx.x * ROWS_PER_BLK;
    for (int i = t; i < ROWS_PER_BLK * DIM; i += 256)
        (&z_s[0][0])[i] = z[row0 * DIM + i];
    // stage per-c constants
    for (int i = t; i < C_CAT; i += 256) {
        c_recip[i]  = d_c.recip[i];
        c_invsig[i] = d_c.invsig[i];
        c_sq[i]     = d_c.sq[i];
        c_base[i]   = d_c.base[i];
        c_k1[i]     = d_c.k1[i];
        c_mB2[i]    = d_c.mB2[i];
        c_ab[i]     = d_c.ab[i];
    }
    __syncthreads();

    const int w = t >> 5;        // warp == row within block
    const int l = t & 31;

    // |z|^2 : each lane sums 2 elements, butterfly reduce
    float p = z_s[w][l] * z_s[w][l] + z_s[w][l + 32] * z_s[w][l + 32];
    #pragma unroll
    for (int o = 16; o; o >>= 1) p += __shfl_xor_sync(0xffffffffu, p, o);
    const float z2 = p;

    // g_k = dot(z_row, mu_k): lane (k,half) does a 32-long partial, fold halves
    {
        const int k = l & 15, h = l >> 4;
        float acc = 0.f;
        #pragma unroll
        for (int d = 0; d < 32; ++d)
            acc = fmaf(z_s[w][h * 32 + d], mu_s[h * 32 + d][k], acc);
        acc += __shfl_xor_sync(0xffffffffu, acc, 16);
        if (h == 0) g_s[w][k] = acc;
    }
    __syncwarp();

    // per-category log_p_zc + online logsumexp
    float m = -INFINITY, ssum = 0.f;
    for (int c = l; c < C_CAT; c += 32) {
        const int ab = c_ab[c];
        const int A = ab & 255, B = (ab >> 8) & 255;
        const float gA = g_s[w][A];
        const float gB = g_s[w][B];
        const float beta_sq = z2 - 2.0f * gB + c_mB2[c];

        float v;
        if (ab & (1 << 16)) {                         // inv_sig == 0 (diag pair)
            v = c_base[c] - 0.5f * beta_sq;
        } else {
            const float nu   = (c_k1[c] - gB + gA) * c_recip[c];
            const float tq   = fmaf(nu * nu, c_invsig[c], -beta_sq);
            const float sq   = c_sq[c];
            const float eta1 = (1.0f - nu) * sq;
            const float eta2 = -nu * sq;
            float cdfd = 0.5f * (erfcf(eta1 * NEG_RSQRT2) - erfcf(eta2 * NEG_RSQRT2));
            cdfd = fminf(fmaxf(cdfd, 1e-16f), 1e30f);
            v = c_base[c] + 0.5f * tq + __logf(cdfd);
        }
        const float nm = fmaxf(m, v);
        ssum = ssum * __expf(m - nm) + __expf(v - nm);
        m = nm;
    }

    // warp-combine (m, ssum)
    #pragma unroll
    for (int o = 16; o; o >>= 1) {
        const float mo = __shfl_xor_sync(0xffffffffu, m, o);
        const float so = __shfl_xor_sync(0xffffffffu, ssum, o);
        const float nm = fmaxf(m, mo);
        ssum = ssum * __expf(m - nm) + so * __expf(mo - nm);
        m = nm;
    }
    if (l == 0) rowres[w] = m + logf(ssum);
    __syncthreads();

    if (t == 0) {
        float s = 0.f;
        #pragma unroll
        for (int r = 0; r < ROWS_PER_BLK; ++r) s += rowres[r];
        d_partials[blockIdx.x] = s;
    }
}

// ---------------------------------------------------------------------------
// Kernel 3: deterministic final reduction -> mean
// ---------------------------------------------------------------------------
__global__ void finalize_kernel(float* __restrict__ out)
{
    __shared__ float red[256];
    const int t = threadIdx.x;
    float s = 0.f;
    for (int i = t; i < MAIN_BLOCKS; i += 256) s += d_partials[i];
    red[t] = s; __syncthreads();
    for (int o = 128; o; o >>= 1) { if (t < o) red[t] += red[t + o]; __syncthreads(); }
    if (t == 0) out[0] = red[0] * (1.0f / (float)NROWS);
}

// ---------------------------------------------------------------------------
extern "C" void kernel_launch(void* const* d_in, const int* in_sizes, int n_in,
                              void* d_out, int out_size)
{
    (void)in_sizes; (void)n_in; (void)out_size;
    const float* z  = (const float*)d_in[0];
    const float* pi = (const float*)d_in[1];
    const float* mu = (const float*)d_in[2];
    float* out = (float*)d_out;

    precompute_kernel<<<1, 256>>>(pi, mu);
    main_kernel<<<MAIN_BLOCKS, 256>>>(z, mu);
    finalize_kernel<<<1, 256>>>(out);
}